// round 4
// baseline (speedup 1.0000x reference)
#include <cuda_runtime.h>
#include <math.h>
#include <cstdint>

#define BB   512
#define SSL  128
#define HH   192
#define VV   256
#define PP   64
#define PHD  16
#define ROWS 8
#define NTH  384
#define NLOC 96     // cols per CTA in split GEMMs (HH/2)

typedef unsigned long long u64;

struct SM {
    float tok  [HH][ROWS];
    float prevb[HH][ROWS];
    float patch[HH][ROWS];
    float sec  [HH][ROWS];
    float phs  [HH][ROWS];
    float succ [HH][ROWS];
    float htmp [HH][ROWS];
    float pwb  [PP][ROWS];
    float phwb [PHD][ROWS];
    float rlog [PHD][ROWS];
    float4 partbuf[NTH][8];
    float gx[2][ROWS];
    float gatev[ROWS];
    float lnmean[ROWS], lnrstd[ROWS];
    int   sidx[ROWS][SSL];
};

__device__ __forceinline__ float gelu_exact(float x) {
    return 0.5f * x * (1.0f + erff(x * 0.70710678118654752440f));
}
__device__ __forceinline__ float sigmoidf_(float x) {
    return 1.0f / (1.0f + expf(-x));
}
__device__ __forceinline__ u64 ffma2u(u64 a, u64 b, u64 c) {
    u64 d;
    asm("fma.rn.f32x2 %0, %1, %2, %3;" : "=l"(d) : "l"(a), "l"(b), "l"(c));
    return d;
}
__device__ __forceinline__ u64 dup2(float w) {
    u64 d;
    asm("mov.b64 %0, {%1, %1};" : "=l"(d) : "f"(w));
    return d;
}
__device__ __forceinline__ uint32_t smem_u32(const void* p) {
    uint32_t a;
    asm("{ .reg .u64 tmp; cvta.to.shared.u64 tmp, %1; cvt.u32.u64 %0, tmp; }"
        : "=r"(a) : "l"(p));
    return a;
}
// store float4 into the SAME smem offset in the peer CTA
__device__ __forceinline__ void st_peer_f4(const void* lptr, uint32_t peer, float4 v) {
    uint32_t la = smem_u32(lptr);
    asm volatile(
        "{ .reg .b32 ra;\n\t"
        "mapa.shared::cluster.u32 ra, %0, %1;\n\t"
        "st.shared::cluster.v4.b32 [ra], {%2, %3, %4, %5}; }"
        :: "r"(la), "r"(peer), "f"(v.x), "f"(v.y), "f"(v.z), "f"(v.w) : "memory");
}
__device__ __forceinline__ void st_peer_f1(const void* lptr, uint32_t peer, float v) {
    uint32_t la = smem_u32(lptr);
    asm volatile(
        "{ .reg .b32 ra;\n\t"
        "mapa.shared::cluster.u32 ra, %0, %1;\n\t"
        "st.shared::cluster.b32 [ra], %2; }"
        :: "r"(la), "r"(peer), "f"(v) : "memory");
}
#define CLB() do {                                                      \
    asm volatile("barrier.cluster.arrive.aligned;" ::: "memory");      \
    asm volatile("barrier.cluster.wait.aligned;"   ::: "memory");      \
} while (0)

// accumulate NIT K-rows into 4col x 8row tile (rows as 4 f32x2 pairs per col)
template<int NIT>
__device__ __forceinline__ void seg(
    u64 (&ac)[4][4],
    const float (*__restrict__ X)[ROWS], const float* __restrict__ W,
    int xrow0, int wrow0, int Ns, int c0)
{
    #pragma unroll
    for (int k = 0; k < NIT; ++k) {
        float4 w = *(const float4*)(W + (size_t)(wrow0 + k) * Ns + c0);
        ulonglong2 xa = *(const ulonglong2*)&X[xrow0 + k][0];
        ulonglong2 xb = *(const ulonglong2*)&X[xrow0 + k][4];
        u64 w0 = dup2(w.x), w1 = dup2(w.y), w2 = dup2(w.z), w3 = dup2(w.w);
        ac[0][0] = ffma2u(w0, xa.x, ac[0][0]); ac[0][1] = ffma2u(w0, xa.y, ac[0][1]);
        ac[0][2] = ffma2u(w0, xb.x, ac[0][2]); ac[0][3] = ffma2u(w0, xb.y, ac[0][3]);
        ac[1][0] = ffma2u(w1, xa.x, ac[1][0]); ac[1][1] = ffma2u(w1, xa.y, ac[1][1]);
        ac[1][2] = ffma2u(w1, xb.x, ac[1][2]); ac[1][3] = ffma2u(w1, xb.y, ac[1][3]);
        ac[2][0] = ffma2u(w2, xa.x, ac[2][0]); ac[2][1] = ffma2u(w2, xa.y, ac[2][1]);
        ac[2][2] = ffma2u(w2, xb.x, ac[2][2]); ac[2][3] = ffma2u(w2, xb.y, ac[2][3]);
        ac[3][0] = ffma2u(w3, xa.x, ac[3][0]); ac[3][1] = ffma2u(w3, xa.y, ac[3][1]);
        ac[3][2] = ffma2u(w3, xb.x, ac[3][2]); ac[3][3] = ffma2u(w3, xb.y, ac[3][3]);
    }
}

#define PART_STORE()                                                    \
    _Pragma("unroll")                                                   \
    for (int c = 0; c < 4; ++c) {                                       \
        float4 f;                                                       \
        ((u64*)&f)[0] = ac[c][0]; ((u64*)&f)[1] = ac[c][1];             \
        s->partbuf[t][2 * c] = f;                                       \
        ((u64*)&f)[0] = ac[c][2]; ((u64*)&f)[1] = ac[c][3];             \
        s->partbuf[t][2 * c + 1] = f;                                   \
    }

// owner threads t < NG*8: g=t>>3, q=t&7; col_local = 4g + (q>>1); h = q&1
template<int NG, int P>
__device__ __forceinline__ float4 reduce_own(const SM* s, int t) {
    int g = t >> 3, q = t & 7;
    float4 sv = s->partbuf[g][q];
    #pragma unroll 8
    for (int p = 1; p < P; ++p) {
        float4 v = s->partbuf[p * NG + g][q];
        sv.x += v.x; sv.y += v.y; sv.z += v.z; sv.w += v.w;
    }
    return sv;
}

__global__ __launch_bounds__(NTH, 1) __cluster_dims__(2, 1, 1)
void spike_recurrence_kernel(
    const int*   __restrict__ input_ids,
    const float* __restrict__ emb,
    const float* __restrict__ sel_W,  const float* __restrict__ sel_b,
    const float* __restrict__ patch_values,
    const float* __restrict__ bind_W1, const float* __restrict__ bind_b1,
    const float* __restrict__ bind_W2, const float* __restrict__ bind_b2,
    const float* __restrict__ phase_embed,
    const float* __restrict__ router_W, const float* __restrict__ router_b,
    const float* __restrict__ succ_W1, const float* __restrict__ succ_b1,
    const float* __restrict__ succ_W2, const float* __restrict__ succ_b2,
    const float* __restrict__ gate_W1, const float* __restrict__ gate_b1,
    const float* __restrict__ gate_W2, const float* __restrict__ gate_b2,
    const float* __restrict__ ln_g,   const float* __restrict__ ln_b,
    const float* __restrict__ dec_W,
    float* __restrict__ out)
{
    extern __shared__ __align__(16) char smraw[];
    SM* s = (SM*)smraw;

    const int t    = threadIdx.x;
    const int lane = t & 31;
    const int warp = t >> 5;
    uint32_t rank;
    asm("mov.u32 %0, %%cluster_ctarank;" : "=r"(rank));
    const uint32_t peer = rank ^ 1u;
    const int pairBase = (blockIdx.x >> 1) * ROWS;   // 8 batch rows per cluster
    const int cb = (int)rank * NLOC;                 // column base for split GEMMs

    for (int i = t; i < ROWS * SSL; i += NTH) {
        int r = i / SSL, ss = i % SSL;
        s->sidx[r][ss] = input_ids[(pairBase + r) * SSL + ss];
    }
    if (t < HH) {
        *(float4*)&s->prevb[t][0] = make_float4(0.f, 0.f, 0.f, 0.f);
        *(float4*)&s->prevb[t][4] = make_float4(0.f, 0.f, 0.f, 0.f);
    }
    __syncthreads();
    CLB();

    const size_t OFF_HID = (size_t)BB * SSL * VV;
    const size_t OFF_PW  = OFF_HID + (size_t)BB * SSL * HH;
    const size_t OFF_PHW = OFF_PW  + (size_t)BB * SSL * PP;
    const size_t OFF_GT  = OFF_PHW + (size_t)BB * SSL * PHD;

    for (int st = 0; st < SSL; ++st) {
        // ---- token embeddings (full, duplicated) -------------------------
        for (int i = t; i < HH * ROWS; i += NTH) {
            int r = i / HH, c = i % HH;
            s->tok[c][r] = emb[(size_t)s->sidx[r][st] * HH + c];
        }
        __syncthreads();

        // ---- sel: full N=64, NG=16, P=24, 8 iters/seg --------------------
        {
            int g = t % 16, p = t / 16, c0 = 4 * g;
            u64 ac[4][4] = {};
            seg<8>(ac, s->tok,   sel_W, p * 8,       p * 8, PP, c0);
            seg<8>(ac, s->prevb, sel_W, p * 8, 192 + p * 8, PP, c0);
            PART_STORE();
        }
        __syncthreads();
        if (t < 128) {
            float4 sv = reduce_own<16, 24>(s, t);
            int g = t >> 3, q = t & 7, col = 4 * g + (q >> 1), h = q & 1;
            float b = sel_b[col];
            sv.x += b; sv.y += b; sv.z += b; sv.w += b;
            *(float4*)&s->pwb[col][h * 4] = sv;
        }
        __syncthreads();
        if (warp < ROWS) {   // softmax over 64, one warp per batch row
            int r = warp;
            float v0 = s->pwb[lane][r], v1 = s->pwb[lane + 32][r];
            float m = fmaxf(v0, v1);
            #pragma unroll
            for (int o = 16; o > 0; o >>= 1) m = fmaxf(m, __shfl_xor_sync(0xffffffffu, m, o));
            float e0 = expf(v0 - m), e1 = expf(v1 - m);
            float sm = e0 + e1;
            #pragma unroll
            for (int o = 16; o > 0; o >>= 1) sm += __shfl_xor_sync(0xffffffffu, sm, o);
            float inv = 1.0f / sm;
            e0 *= inv; e1 *= inv;
            s->pwb[lane][r] = e0; s->pwb[lane + 32][r] = e1;
            if ((r >> 2) == (int)rank) {
                size_t ob = OFF_PW + ((size_t)(pairBase + r) * SSL + st) * PP;
                out[ob + lane] = e0; out[ob + lane + 32] = e1;
            }
        }
        __syncthreads();

        // ---- patch = pw @ patch_values  (split: NG=24, P=16, 4 iters) ----
        {
            int g = t % 24, p = t / 24, c0 = cb + 4 * g;
            u64 ac[4][4] = {};
            seg<4>(ac, s->pwb, patch_values, p * 4, p * 4, HH, c0);
            PART_STORE();
        }
        __syncthreads();
        if (t < 192) {
            float4 sv = reduce_own<24, 16>(s, t);
            int g = t >> 3, q = t & 7, gcol = cb + 4 * g + (q >> 1), h = q & 1;
            *(float4*)&s->patch[gcol][h * 4] = sv;
            st_peer_f4(&s->patch[gcol][h * 4], peer, sv);
        }
        CLB();

        // ---- bind1 (split: NG=24, P=16, 12 iters/seg) --------------------
        {
            int g = t % 24, p = t / 24, c0 = cb + 4 * g;
            u64 ac[4][4] = {};
            seg<12>(ac, s->tok,   bind_W1, p * 12,        p * 12, HH, c0);
            seg<12>(ac, s->patch, bind_W1, p * 12,  192 + p * 12, HH, c0);
            seg<12>(ac, s->prevb, bind_W1, p * 12,  384 + p * 12, HH, c0);
            PART_STORE();
        }
        __syncthreads();
        if (t < 192) {
            float4 sv = reduce_own<24, 16>(s, t);
            int g = t >> 3, q = t & 7, gcol = cb + 4 * g + (q >> 1), h = q & 1;
            float b = bind_b1[gcol];
            float4 hv;
            hv.x = gelu_exact(sv.x + b); hv.y = gelu_exact(sv.y + b);
            hv.z = gelu_exact(sv.z + b); hv.w = gelu_exact(sv.w + b);
            *(float4*)&s->htmp[gcol][h * 4] = hv;
            st_peer_f4(&s->htmp[gcol][h * 4], peer, hv);
        }
        CLB();

        // ---- bind2 -> tanh -> sec (split) --------------------------------
        {
            int g = t % 24, p = t / 24, c0 = cb + 4 * g;
            u64 ac[4][4] = {};
            seg<12>(ac, s->htmp, bind_W2, p * 12, p * 12, HH, c0);
            PART_STORE();
        }
        __syncthreads();
        if (t < 192) {
            float4 sv = reduce_own<24, 16>(s, t);
            int g = t >> 3, q = t & 7, gcol = cb + 4 * g + (q >> 1), h = q & 1;
            float b = bind_b2[gcol];
            float4 hv;
            hv.x = tanhf(sv.x + b); hv.y = tanhf(sv.y + b);
            hv.z = tanhf(sv.z + b); hv.w = tanhf(sv.w + b);
            *(float4*)&s->sec[gcol][h * 4] = hv;
            st_peer_f4(&s->sec[gcol][h * 4], peer, hv);
        }
        CLB();

        // ---- router: full N=16, NG=4, P=96, 2 iters/seg ------------------
        {
            int g = t % 4, p = t / 4, c0 = 4 * g;
            u64 ac[4][4] = {};
            seg<2>(ac, s->sec,   router_W, p * 2,       p * 2, PHD, c0);
            seg<2>(ac, s->prevb, router_W, p * 2, 192 + p * 2, PHD, c0);
            PART_STORE();
        }
        __syncthreads();
        if (t < 32) {
            float4 sv = reduce_own<4, 96>(s, t);
            int g = t >> 3, q = t & 7, col = 4 * g + (q >> 1), h = q & 1;
            float b = router_b[col];
            sv.x += b; sv.y += b; sv.z += b; sv.w += b;
            *(float4*)&s->rlog[col][h * 4] = sv;
        }
        __syncthreads();
        if (t < ROWS) {
            int r = t;
            float m = -1e30f;
            #pragma unroll
            for (int c = 0; c < PHD; ++c) m = fmaxf(m, s->rlog[c][r]);
            float sm = 0.f;
            float e[PHD];
            #pragma unroll
            for (int c = 0; c < PHD; ++c) { e[c] = expf(s->rlog[c][r] - m); sm += e[c]; }
            float inv = 1.0f / sm;
            bool own = ((r >> 2) == (int)rank);
            size_t ob = OFF_PHW + ((size_t)(pairBase + r) * SSL + st) * PHD;
            #pragma unroll
            for (int c = 0; c < PHD; ++c) {
                float v = e[c] * inv;
                s->phwb[c][r] = v;
                if (own) out[ob + c] = v;
            }
        }
        __syncthreads();

        // ---- phs = phw @ phase_embed (split: NG=24, P=16, 1 iter) --------
        {
            int g = t % 24, p = t / 24, c0 = cb + 4 * g;
            u64 ac[4][4] = {};
            seg<1>(ac, s->phwb, phase_embed, p, p, HH, c0);
            PART_STORE();
        }
        __syncthreads();
        if (t < 192) {
            float4 sv = reduce_own<24, 16>(s, t);
            int g = t >> 3, q = t & 7, gcol = cb + 4 * g + (q >> 1), h = q & 1;
            *(float4*)&s->phs[gcol][h * 4] = sv;
            st_peer_f4(&s->phs[gcol][h * 4], peer, sv);
        }
        CLB();

        // ---- succ1 (split) ------------------------------------------------
        {
            int g = t % 24, p = t / 24, c0 = cb + 4 * g;
            u64 ac[4][4] = {};
            seg<12>(ac, s->sec,   succ_W1, p * 12,        p * 12, HH, c0);
            seg<12>(ac, s->patch, succ_W1, p * 12,  192 + p * 12, HH, c0);
            seg<12>(ac, s->phs,   succ_W1, p * 12,  384 + p * 12, HH, c0);
            PART_STORE();
        }
        __syncthreads();
        if (t < 192) {
            float4 sv = reduce_own<24, 16>(s, t);
            int g = t >> 3, q = t & 7, gcol = cb + 4 * g + (q >> 1), h = q & 1;
            float b = succ_b1[gcol];
            float4 hv;
            hv.x = gelu_exact(sv.x + b); hv.y = gelu_exact(sv.y + b);
            hv.z = gelu_exact(sv.z + b); hv.w = gelu_exact(sv.w + b);
            *(float4*)&s->htmp[gcol][h * 4] = hv;
            st_peer_f4(&s->htmp[gcol][h * 4], peer, hv);
        }
        CLB();

        // ---- succ2 -> tanh -> succ (split) --------------------------------
        {
            int g = t % 24, p = t / 24, c0 = cb + 4 * g;
            u64 ac[4][4] = {};
            seg<12>(ac, s->htmp, succ_W2, p * 12, p * 12, HH, c0);
            PART_STORE();
        }
        __syncthreads();
        if (t < 192) {
            float4 sv = reduce_own<24, 16>(s, t);
            int g = t >> 3, q = t & 7, gcol = cb + 4 * g + (q >> 1), h = q & 1;
            float b = succ_b2[gcol];
            float4 hv;
            hv.x = tanhf(sv.x + b); hv.y = tanhf(sv.y + b);
            hv.z = tanhf(sv.z + b); hv.w = tanhf(sv.w + b);
            *(float4*)&s->succ[gcol][h * 4] = hv;
            st_peer_f4(&s->succ[gcol][h * 4], peer, hv);
        }
        CLB();

        // ---- gate (split; local htmp only, exchange row-partials) ---------
        {
            int g = t % 24, p = t / 24, c0 = cb + 4 * g;
            u64 ac[4][4] = {};
            seg<12>(ac, s->succ,  gate_W1, p * 12,        p * 12, HH, c0);
            seg<12>(ac, s->prevb, gate_W1, p * 12,  192 + p * 12, HH, c0);
            PART_STORE();
        }
        __syncthreads();
        if (t < 192) {
            float4 sv = reduce_own<24, 16>(s, t);
            int g = t >> 3, q = t & 7, gcol = cb + 4 * g + (q >> 1), h = q & 1;
            float b = gate_b1[gcol];
            float w2 = gate_W2[gcol];
            float4 hv;
            hv.x = gelu_exact(sv.x + b) * w2; hv.y = gelu_exact(sv.y + b) * w2;
            hv.z = gelu_exact(sv.z + b) * w2; hv.w = gelu_exact(sv.w + b) * w2;
            *(float4*)&s->htmp[gcol][h * 4] = hv;
        }
        __syncthreads();
        if (warp < ROWS) {   // per-row partial over this CTA's 96 cols
            int r = warp;
            float sg = s->htmp[cb + lane][r] + s->htmp[cb + lane + 32][r]
                     + s->htmp[cb + lane + 64][r];
            #pragma unroll
            for (int o = 16; o > 0; o >>= 1) sg += __shfl_xor_sync(0xffffffffu, sg, o);
            if (lane == 0) {
                s->gx[0][r] = sg;
                st_peer_f1(&s->gx[1][r], peer, sg);
            }
        }
        CLB();
        if (t < ROWS) {
            float gv = sigmoidf_(s->gx[0][t] + s->gx[1][t] + gate_b2[0]);
            s->gatev[t] = gv;
            if ((t >> 2) == (int)rank)
                out[OFF_GT + (size_t)(pairBase + t) * SSL + st] = gv;
        }
        __syncthreads();

        // ---- hidden blend (full, duplicated) -------------------------------
        if (t < HH) {
            #pragma unroll
            for (int h = 0; h < 2; ++h) {
                float4 svv = *(const float4*)&s->succ[t][h * 4];
                float4 pv  = *(const float4*)&s->prevb[t][h * 4];
                float4 hv;
                float g0 = s->gatev[h * 4 + 0], g1 = s->gatev[h * 4 + 1];
                float g2 = s->gatev[h * 4 + 2], g3 = s->gatev[h * 4 + 3];
                hv.x = g0 * svv.x + (1.f - g0) * pv.x;
                hv.y = g1 * svv.y + (1.f - g1) * pv.y;
                hv.z = g2 * svv.z + (1.f - g2) * pv.z;
                hv.w = g3 * svv.w + (1.f - g3) * pv.w;
                *(float4*)&s->htmp[t][h * 4] = hv;
            }
        }
        __syncthreads();
        if (warp < ROWS) {
            int r = warp;
            float sm = 0.f, sq = 0.f;
            #pragma unroll
            for (int j = 0; j < 6; ++j) {
                float v = s->htmp[lane + 32 * j][r];
                sm += v; sq += v * v;
            }
            #pragma unroll
            for (int o = 16; o > 0; o >>= 1) {
                sm += __shfl_xor_sync(0xffffffffu, sm, o);
                sq += __shfl_xor_sync(0xffffffffu, sq, o);
            }
            if (lane == 0) {
                float mean = sm * (1.0f / HH);
                float var  = sq * (1.0f / HH) - mean * mean;
                s->lnmean[r] = mean;
                s->lnrstd[r] = rsqrtf(var + 1e-5f);
            }
        }
        __syncthreads();
        if (t < HH) {
            float g = ln_g[t], bb = ln_b[t];
            #pragma unroll
            for (int h = 0; h < 2; ++h) {
                float4 hv = *(const float4*)&s->htmp[t][h * 4];
                float4 o4;
                o4.x = (hv.x - s->lnmean[h * 4 + 0]) * s->lnrstd[h * 4 + 0] * g + bb;
                o4.y = (hv.y - s->lnmean[h * 4 + 1]) * s->lnrstd[h * 4 + 1] * g + bb;
                o4.z = (hv.z - s->lnmean[h * 4 + 2]) * s->lnrstd[h * 4 + 2] * g + bb;
                o4.w = (hv.w - s->lnmean[h * 4 + 3]) * s->lnrstd[h * 4 + 3] * g + bb;
                *(float4*)&s->prevb[t][h * 4] = o4;
            }
            // write own 4 rows of hidden
            #pragma unroll
            for (int j = 0; j < 4; ++j) {
                int r = (int)rank * 4 + j;
                out[OFF_HID + ((size_t)(pairBase + r) * SSL + st) * HH + t] =
                    s->prevb[t][r];
            }
        }
        __syncthreads();

        // ---- decoder logits (split: NG=32, P=12, 16 iters) -----------------
        {
            int g = t % 32, p = t / 32, c0 = (int)rank * 128 + 4 * g;
            u64 ac[4][4] = {};
            seg<16>(ac, s->prevb, dec_W, p * 16, p * 16, VV, c0);
            PART_STORE();
        }
        __syncthreads();
        if (t < 256) {
            float4 sv = reduce_own<32, 12>(s, t);
            int g = t >> 3, q = t & 7, col = (int)rank * 128 + 4 * g + (q >> 1), h = q & 1;
            #pragma unroll
            for (int j = 0; j < 4; ++j) {
                int r = h * 4 + j;
                float v = (j == 0) ? sv.x : (j == 1) ? sv.y : (j == 2) ? sv.z : sv.w;
                out[((size_t)(pairBase + r) * SSL + st) * VV + col] = v;
            }
        }
        __syncthreads();
    }
    CLB();
}

extern "C" void kernel_launch(void* const* d_in, const int* in_sizes, int n_in,
                              void* d_out, int out_size) {
    const int*   input_ids    = (const int*)  d_in[0];
    const float* emb          = (const float*)d_in[1];
    const float* sel_W        = (const float*)d_in[2];
    const float* sel_b        = (const float*)d_in[3];
    const float* patch_values = (const float*)d_in[4];
    const float* bind_W1      = (const float*)d_in[5];
    const float* bind_b1      = (const float*)d_in[6];
    const float* bind_W2      = (const float*)d_in[7];
    const float* bind_b2      = (const float*)d_in[8];
    const float* phase_embed  = (const float*)d_in[9];
    const float* router_W     = (const float*)d_in[10];
    const float* router_b     = (const float*)d_in[11];
    const float* succ_W1      = (const float*)d_in[12];
    const float* succ_b1      = (const float*)d_in[13];
    const float* succ_W2      = (const float*)d_in[14];
    const float* succ_b2      = (const float*)d_in[15];
    const float* gate_W1      = (const float*)d_in[16];
    const float* gate_b1      = (const float*)d_in[17];
    const float* gate_W2      = (const float*)d_in[18];
    const float* gate_b2      = (const float*)d_in[19];
    const float* ln_g         = (const float*)d_in[20];
    const float* ln_b         = (const float*)d_in[21];
    const float* dec_W        = (const float*)d_in[22];
    float* out = (float*)d_out;

    cudaFuncSetAttribute(spike_recurrence_kernel,
                         cudaFuncAttributeMaxDynamicSharedMemorySize,
                         (int)sizeof(SM));

    spike_recurrence_kernel<<<BB * 2 / ROWS, NTH, sizeof(SM)>>>(
        input_ids, emb, sel_W, sel_b, patch_values,
        bind_W1, bind_b1, bind_W2, bind_b2,
        phase_embed, router_W, router_b,
        succ_W1, succ_b1, succ_W2, succ_b2,
        gate_W1, gate_b1, gate_W2, gate_b2,
        ln_g, ln_b, dec_W, out);
}

// round 5
// speedup vs baseline: 1.3042x; 1.3042x over previous
#include <cuda_runtime.h>
#include <math.h>

#define BB  512
#define SSL 128
#define HH  192
#define VV  256
#define PP  64
#define PHD 16
#define BT  4
#define NTH 768

struct SMLayout {
    float tok  [HH][BT];
    float prevb[HH][BT];
    float patch[HH][BT];
    float sec  [HH][BT];
    float phs  [HH][BT];
    float succ [HH][BT];
    float htmp [HH][BT];
    float4 partbuf[NTH][4];     // per-thread 4-col x 4-row partials
    float pwb [PP][BT];
    float rlog[PHD][BT];
    float phwb[PHD][BT];
    float gatev[BT];
    float lnmean[BT], lnrstd[BT];
    int   sidx[BT][SSL];
};

__device__ __forceinline__ float gelu_exact(float x) {
    return 0.5f * x * (1.0f + erff(x * 0.70710678118654752440f));
}
__device__ __forceinline__ float sigmoidf_(float x) {
    return 1.0f / (1.0f + expf(-x));
}
__device__ __forceinline__ void fma4(float4& a, float w, const float4& x) {
    a.x = fmaf(w, x.x, a.x); a.y = fmaf(w, x.y, a.y);
    a.z = fmaf(w, x.z, a.z); a.w = fmaf(w, x.w, a.w);
}

template<int NIT>
__device__ __forceinline__ void seg4(
    float4& A0, float4& A1, float4& A2, float4& A3,
    const float (*__restrict__ X)[BT], const float* __restrict__ W,
    int xrow0, int wrow0, int Ns, int c0)
{
    #pragma unroll 4
    for (int k = 0; k < NIT; ++k) {
        float4 w = *(const float4*)(W + (size_t)(wrow0 + k) * Ns + c0);
        float4 x = *(const float4*)&X[xrow0 + k][0];
        fma4(A0, w.x, x); fma4(A1, w.y, x); fma4(A2, w.z, x); fma4(A3, w.w, x);
    }
}

#define PART_STORE()                                                \
    s->partbuf[t][0] = A0; s->partbuf[t][1] = A1;                   \
    s->partbuf[t][2] = A2; s->partbuf[t][3] = A3;

#define REDUCE_SUM(NGP, PCH)                                        \
    int gg = t >> 2, cc = t & 3;                                    \
    float4 sv = s->partbuf[gg][cc];                                 \
    _Pragma("unroll 8")                                             \
    for (int pp = 1; pp < (PCH); ++pp) {                            \
        float4 v = s->partbuf[pp * (NGP) + gg][cc];                 \
        sv.x += v.x; sv.y += v.y; sv.z += v.z; sv.w += v.w;         \
    }

__global__ __launch_bounds__(NTH, 1)
void spike_recurrence_kernel(
    const int*   __restrict__ input_ids,
    const float* __restrict__ emb,
    const float* __restrict__ sel_W,  const float* __restrict__ sel_b,
    const float* __restrict__ patch_values,
    const float* __restrict__ bind_W1, const float* __restrict__ bind_b1,
    const float* __restrict__ bind_W2, const float* __restrict__ bind_b2,
    const float* __restrict__ phase_embed,
    const float* __restrict__ router_W, const float* __restrict__ router_b,
    const float* __restrict__ succ_W1, const float* __restrict__ succ_b1,
    const float* __restrict__ succ_W2, const float* __restrict__ succ_b2,
    const float* __restrict__ gate_W1, const float* __restrict__ gate_b1,
    const float* __restrict__ gate_W2, const float* __restrict__ gate_b2,
    const float* __restrict__ ln_g,   const float* __restrict__ ln_b,
    const float* __restrict__ dec_W,
    float* __restrict__ out)
{
    extern __shared__ __align__(16) char smraw[];
    SMLayout* s = (SMLayout*)smraw;

    const int t    = threadIdx.x;
    const int lane = t & 31;
    const int warp = t >> 5;
    const int bbase = blockIdx.x * BT;
    const float4 z4 = make_float4(0.f, 0.f, 0.f, 0.f);

    for (int i = t; i < BT * SSL; i += NTH) {
        int r = i / SSL, ss = i % SSL;
        s->sidx[r][ss] = input_ids[(bbase + r) * SSL + ss];
    }
    if (t < HH) *(float4*)&s->prevb[t][0] = z4;
    __syncthreads();

    const size_t OFF_HID = (size_t)BB * SSL * VV;
    const size_t OFF_PW  = OFF_HID + (size_t)BB * SSL * HH;
    const size_t OFF_PHW = OFF_PW  + (size_t)BB * SSL * PP;
    const size_t OFF_GT  = OFF_PHW + (size_t)BB * SSL * PHD;

    for (int st = 0; st < SSL; ++st) {
        // ---- token embedding gather (768 threads = 1 iter) ---------------
        {
            int r = t / HH, c = t % HH;
            if (r < BT) s->tok[c][r] = emb[(size_t)s->sidx[r][st] * HH + c];
        }
        __syncthreads();

        // ---- sel: [tok,prev] @ sel_W  (N=64, NG=16, P=48, 8 rows each) ----
        {
            int g = t % 16, p = t / 16, c0 = 4 * g;   // p in 0..47
            float4 A0 = z4, A1 = z4, A2 = z4, A3 = z4;
            if (p < 24) seg4<8>(A0, A1, A2, A3, s->tok,   sel_W, p * 8,        p * 8,       PP, c0);
            else        seg4<8>(A0, A1, A2, A3, s->prevb, sel_W, (p - 24) * 8, 192 + (p - 24) * 8, PP, c0);
            PART_STORE();
        }
        __syncthreads();
        if (t < PP) {
            REDUCE_SUM(16, 48);
            float bias = sel_b[t];
            sv.x += bias; sv.y += bias; sv.z += bias; sv.w += bias;
            *(float4*)&s->pwb[t][0] = sv;
        }
        __syncthreads();
        if (warp < BT) {  // softmax over 64, one warp per batch row
            int r = warp;
            float v0 = s->pwb[lane][r], v1 = s->pwb[lane + 32][r];
            float m = fmaxf(v0, v1);
            #pragma unroll
            for (int o = 16; o > 0; o >>= 1) m = fmaxf(m, __shfl_xor_sync(0xffffffffu, m, o));
            float e0 = expf(v0 - m), e1 = expf(v1 - m);
            float sm = e0 + e1;
            #pragma unroll
            for (int o = 16; o > 0; o >>= 1) sm += __shfl_xor_sync(0xffffffffu, sm, o);
            float inv = 1.0f / sm;
            e0 *= inv; e1 *= inv;
            s->pwb[lane][r] = e0; s->pwb[lane + 32][r] = e1;
            size_t ob = OFF_PW + ((size_t)(bbase + r) * SSL + st) * PP;
            out[ob + lane] = e0; out[ob + lane + 32] = e1;
        }
        __syncthreads();

        // ---- patch = pw @ patch_values  (NG=48, P=16, 4 rows each) --------
        {
            int g = t % 48, p = t / 48, c0 = 4 * g;
            float4 A0 = z4, A1 = z4, A2 = z4, A3 = z4;
            seg4<4>(A0, A1, A2, A3, s->pwb, patch_values, p * 4, p * 4, HH, c0);
            PART_STORE();
        }
        __syncthreads();
        if (t < HH) {
            REDUCE_SUM(48, 16);
            *(float4*)&s->patch[t][0] = sv;
        }
        __syncthreads();

        // ---- bind1: [tok,patch,prev] @ bind_W1 -> gelu  (P=16, 12/seg) ----
        {
            int g = t % 48, p = t / 48, c0 = 4 * g;
            float4 A0 = z4, A1 = z4, A2 = z4, A3 = z4;
            seg4<12>(A0, A1, A2, A3, s->tok,   bind_W1, p * 12,        p * 12, HH, c0);
            seg4<12>(A0, A1, A2, A3, s->patch, bind_W1, p * 12,  192 + p * 12, HH, c0);
            seg4<12>(A0, A1, A2, A3, s->prevb, bind_W1, p * 12,  384 + p * 12, HH, c0);
            PART_STORE();
        }
        __syncthreads();
        if (t < HH) {
            REDUCE_SUM(48, 16);
            float b1 = bind_b1[t];
            float4 h;
            h.x = gelu_exact(sv.x + b1); h.y = gelu_exact(sv.y + b1);
            h.z = gelu_exact(sv.z + b1); h.w = gelu_exact(sv.w + b1);
            *(float4*)&s->htmp[t][0] = h;
        }
        __syncthreads();

        // ---- bind2: htmp @ bind_W2 -> tanh  (P=16, 12 rows) ---------------
        {
            int g = t % 48, p = t / 48, c0 = 4 * g;
            float4 A0 = z4, A1 = z4, A2 = z4, A3 = z4;
            seg4<12>(A0, A1, A2, A3, s->htmp, bind_W2, p * 12, p * 12, HH, c0);
            PART_STORE();
        }
        __syncthreads();
        if (t < HH) {
            REDUCE_SUM(48, 16);
            float b2 = bind_b2[t];
            float4 h;
            h.x = tanhf(sv.x + b2); h.y = tanhf(sv.y + b2);
            h.z = tanhf(sv.z + b2); h.w = tanhf(sv.w + b2);
            *(float4*)&s->sec[t][0] = h;
        }
        __syncthreads();

        // ---- router: [sec,prev] @ router_W  (N=16, NG=4, P=96; t<384) -----
        if (t < 384) {
            int g = t % 4, p = t / 4, c0 = 4 * g;
            float4 A0 = z4, A1 = z4, A2 = z4, A3 = z4;
            seg4<2>(A0, A1, A2, A3, s->sec,   router_W, p * 2,       p * 2, PHD, c0);
            seg4<2>(A0, A1, A2, A3, s->prevb, router_W, p * 2, 192 + p * 2, PHD, c0);
            PART_STORE();
        }
        __syncthreads();
        if (t < PHD) {
            REDUCE_SUM(4, 96);
            float bias = router_b[t];
            sv.x += bias; sv.y += bias; sv.z += bias; sv.w += bias;
            *(float4*)&s->rlog[t][0] = sv;
        }
        __syncthreads();
        if (t < BT) {
            int r = t;
            float m = -1e30f;
            #pragma unroll
            for (int c = 0; c < PHD; ++c) m = fmaxf(m, s->rlog[c][r]);
            float sm = 0.f;
            float e[PHD];
            #pragma unroll
            for (int c = 0; c < PHD; ++c) { e[c] = expf(s->rlog[c][r] - m); sm += e[c]; }
            float inv = 1.0f / sm;
            size_t ob = OFF_PHW + ((size_t)(bbase + r) * SSL + st) * PHD;
            #pragma unroll
            for (int c = 0; c < PHD; ++c) {
                float v = e[c] * inv;
                s->phwb[c][r] = v;
                out[ob + c] = v;
            }
        }
        __syncthreads();

        // ---- phs = phw @ phase_embed  (NG=48, P=16, 1 row each) -----------
        {
            int g = t % 48, p = t / 48, c0 = 4 * g;
            float4 A0 = z4, A1 = z4, A2 = z4, A3 = z4;
            seg4<1>(A0, A1, A2, A3, s->phwb, phase_embed, p, p, HH, c0);
            PART_STORE();
        }
        __syncthreads();
        if (t < HH) {
            REDUCE_SUM(48, 16);
            *(float4*)&s->phs[t][0] = sv;
        }
        __syncthreads();

        // ---- succ1: [sec,patch,phs] @ succ_W1 -> gelu ---------------------
        {
            int g = t % 48, p = t / 48, c0 = 4 * g;
            float4 A0 = z4, A1 = z4, A2 = z4, A3 = z4;
            seg4<12>(A0, A1, A2, A3, s->sec,   succ_W1, p * 12,        p * 12, HH, c0);
            seg4<12>(A0, A1, A2, A3, s->patch, succ_W1, p * 12,  192 + p * 12, HH, c0);
            seg4<12>(A0, A1, A2, A3, s->phs,   succ_W1, p * 12,  384 + p * 12, HH, c0);
            PART_STORE();
        }
        __syncthreads();
        if (t < HH) {
            REDUCE_SUM(48, 16);
            float b1 = succ_b1[t];
            float4 h;
            h.x = gelu_exact(sv.x + b1); h.y = gelu_exact(sv.y + b1);
            h.z = gelu_exact(sv.z + b1); h.w = gelu_exact(sv.w + b1);
            *(float4*)&s->htmp[t][0] = h;
        }
        __syncthreads();

        // ---- succ2: htmp @ succ_W2 -> tanh ---------------------------------
        {
            int g = t % 48, p = t / 48, c0 = 4 * g;
            float4 A0 = z4, A1 = z4, A2 = z4, A3 = z4;
            seg4<12>(A0, A1, A2, A3, s->htmp, succ_W2, p * 12, p * 12, HH, c0);
            PART_STORE();
        }
        __syncthreads();
        if (t < HH) {
            REDUCE_SUM(48, 16);
            float b2 = succ_b2[t];
            float4 h;
            h.x = tanhf(sv.x + b2); h.y = tanhf(sv.y + b2);
            h.z = tanhf(sv.z + b2); h.w = tanhf(sv.w + b2);
            *(float4*)&s->succ[t][0] = h;
        }
        __syncthreads();

        // ---- gate: [succ,prev] @ gate_W1 -> gelu * gate_W2  (P=16, 12/seg) -
        {
            int g = t % 48, p = t / 48, c0 = 4 * g;
            float4 A0 = z4, A1 = z4, A2 = z4, A3 = z4;
            seg4<12>(A0, A1, A2, A3, s->succ,  gate_W1, p * 12,        p * 12, HH, c0);
            seg4<12>(A0, A1, A2, A3, s->prevb, gate_W1, p * 12,  192 + p * 12, HH, c0);
            PART_STORE();
        }
        __syncthreads();
        if (t < HH) {
            REDUCE_SUM(48, 16);
            float b1 = gate_b1[t];
            float w2 = gate_W2[t];
            float4 h;
            h.x = gelu_exact(sv.x + b1) * w2; h.y = gelu_exact(sv.y + b1) * w2;
            h.z = gelu_exact(sv.z + b1) * w2; h.w = gelu_exact(sv.w + b1) * w2;
            *(float4*)&s->htmp[t][0] = h;
        }
        __syncthreads();
        if (warp < BT) {
            int r = warp;
            float sg = 0.f;
            #pragma unroll
            for (int j = 0; j < 6; ++j) sg += s->htmp[lane + 32 * j][r];
            #pragma unroll
            for (int o = 16; o > 0; o >>= 1) sg += __shfl_xor_sync(0xffffffffu, sg, o);
            if (lane == 0) {
                float gv = sigmoidf_(sg + gate_b2[0]);
                s->gatev[r] = gv;
                out[OFF_GT + (size_t)(bbase + r) * SSL + st] = gv;
            }
        }
        __syncthreads();

        // ---- hidden blend + LayerNorm ---------------------------------------
        if (t < HH) {
            float4 svv = *(const float4*)&s->succ[t][0];
            float4 pv  = *(const float4*)&s->prevb[t][0];
            float4 h;
            h.x = s->gatev[0] * svv.x + (1.f - s->gatev[0]) * pv.x;
            h.y = s->gatev[1] * svv.y + (1.f - s->gatev[1]) * pv.y;
            h.z = s->gatev[2] * svv.z + (1.f - s->gatev[2]) * pv.z;
            h.w = s->gatev[3] * svv.w + (1.f - s->gatev[3]) * pv.w;
            *(float4*)&s->htmp[t][0] = h;
        }
        __syncthreads();
        if (warp < BT) {
            int r = warp;
            float sm = 0.f, sq = 0.f;
            #pragma unroll
            for (int j = 0; j < 6; ++j) {
                float v = s->htmp[lane + 32 * j][r];
                sm += v; sq += v * v;
            }
            #pragma unroll
            for (int o = 16; o > 0; o >>= 1) {
                sm += __shfl_xor_sync(0xffffffffu, sm, o);
                sq += __shfl_xor_sync(0xffffffffu, sq, o);
            }
            if (lane == 0) {
                float mean = sm * (1.0f / HH);
                float var  = sq * (1.0f / HH) - mean * mean;
                s->lnmean[r] = mean;
                s->lnrstd[r] = rsqrtf(var + 1e-5f);
            }
        }
        __syncthreads();
        if (t < HH) {
            float g = ln_g[t], bb = ln_b[t];
            float4 h = *(const float4*)&s->htmp[t][0];
            float4 o;
            o.x = (h.x - s->lnmean[0]) * s->lnrstd[0] * g + bb;
            o.y = (h.y - s->lnmean[1]) * s->lnrstd[1] * g + bb;
            o.z = (h.z - s->lnmean[2]) * s->lnrstd[2] * g + bb;
            o.w = (h.w - s->lnmean[3]) * s->lnrstd[3] * g + bb;
            *(float4*)&s->prevb[t][0] = o;   // carry for next step
            #pragma unroll
            for (int r = 0; r < BT; ++r)
                out[OFF_HID + ((size_t)(bbase + r) * SSL + st) * HH + t] =
                    (r == 0) ? o.x : (r == 1) ? o.y : (r == 2) ? o.z : o.w;
        }
        __syncthreads();

        // ---- decoder logits  (N=256, NG=64, P=12, 16 rows each) ------------
        {
            int g = t % 64, p = t / 64, c0 = 4 * g;
            float4 A0 = z4, A1 = z4, A2 = z4, A3 = z4;
            seg4<16>(A0, A1, A2, A3, s->prevb, dec_W, p * 16, p * 16, VV, c0);
            PART_STORE();
        }
        __syncthreads();
        if (t < VV) {
            REDUCE_SUM(64, 12);
            #pragma unroll
            for (int r = 0; r < BT; ++r) {
                size_t ob = ((size_t)(bbase + r) * SSL + st) * VV;
                float v = (r == 0) ? sv.x : (r == 1) ? sv.y : (r == 2) ? sv.z : sv.w;
                out[ob + t] = v;
            }
        }
        __syncthreads();
    }
}

extern "C" void kernel_launch(void* const* d_in, const int* in_sizes, int n_in,
                              void* d_out, int out_size) {
    const int*   input_ids    = (const int*)  d_in[0];
    const float* emb          = (const float*)d_in[1];
    const float* sel_W        = (const float*)d_in[2];
    const float* sel_b        = (const float*)d_in[3];
    const float* patch_values = (const float*)d_in[4];
    const float* bind_W1      = (const float*)d_in[5];
    const float* bind_b1      = (const float*)d_in[6];
    const float* bind_W2      = (const float*)d_in[7];
    const float* bind_b2      = (const float*)d_in[8];
    const float* phase_embed  = (const float*)d_in[9];
    const float* router_W     = (const float*)d_in[10];
    const float* router_b     = (const float*)d_in[11];
    const float* succ_W1      = (const float*)d_in[12];
    const float* succ_b1      = (const float*)d_in[13];
    const float* succ_W2      = (const float*)d_in[14];
    const float* succ_b2      = (const float*)d_in[15];
    const float* gate_W1      = (const float*)d_in[16];
    const float* gate_b1      = (const float*)d_in[17];
    const float* gate_W2      = (const float*)d_in[18];
    const float* gate_b2      = (const float*)d_in[19];
    const float* ln_g         = (const float*)d_in[20];
    const float* ln_b         = (const float*)d_in[21];
    const float* dec_W        = (const float*)d_in[22];
    float* out = (float*)d_out;

    cudaFuncSetAttribute(spike_recurrence_kernel,
                         cudaFuncAttributeMaxDynamicSharedMemorySize,
                         (int)sizeof(SMLayout));

    spike_recurrence_kernel<<<BB / BT, NTH, sizeof(SMLayout)>>>(
        input_ids, emb, sel_W, sel_b, patch_values,
        bind_W1, bind_b1, bind_W2, bind_b2,
        phase_embed, router_W, router_b,
        succ_W1, succ_b1, succ_W2, succ_b2,
        gate_W1, gate_b1, gate_W2, gate_b2,
        ln_g, ln_b, dec_W, out);
}

// round 6
// speedup vs baseline: 2.0031x; 1.5358x over previous
#include <cuda_runtime.h>
#include <math.h>
#include <cstdint>

#define BB  512
#define SSL 128
#define HH  192
#define VV  256
#define PP  64
#define PHD 16
#define BT  4
#define NTH 384

typedef unsigned long long u64;

// Precomputed folded weights (device globals; filled by precompute_kernel each launch)
__device__ float TB_SEL[VV][PP];    // emb @ sel_W[0:192]
__device__ float TB_BIND[VV][HH];   // emb @ bind_W1[0:192]
__device__ float M1[PP][HH];        // patch_values @ bind_W1[192:384]
__device__ float M2[PP][HH];        // patch_values @ succ_W1[192:384]
__device__ float M3[PHD][HH];       // phase_embed  @ succ_W1[384:576]

struct SMLayout {
    float prevb[HH][BT];
    float sec  [HH][BT];
    float succ [HH][BT];
    float htmp [HH][BT];
    float tsel [PP][BT];
    float tbind[HH][BT];
    float pwb  [PP][BT];
    float phwb [PHD][BT];
    float rlog [PHD][BT];
    float4 partbuf[NTH][4];
    float gatev[BT];
    float lnmean[BT], lnrstd[BT];
    int   sidx[BT][SSL];
};

__device__ __forceinline__ float gelu_exact(float x) {
    return 0.5f * x * (1.0f + erff(x * 0.70710678118654752440f));
}
__device__ __forceinline__ float sigmoidf_(float x) {
    return 1.0f / (1.0f + expf(-x));
}
__device__ __forceinline__ u64 ffma2u(u64 a, u64 b, u64 c) {
    u64 d;
    asm("fma.rn.f32x2 %0, %1, %2, %3;" : "=l"(d) : "l"(a), "l"(b), "l"(c));
    return d;
}
__device__ __forceinline__ u64 dup2(float w) {
    u64 d;
    asm("mov.b64 %0, {%1, %1};" : "=l"(d) : "f"(w));
    return d;
}

// 4 cols x 4 rows tile; rows held as 2 f32x2 pairs per column.
// ac[c][0] = (r0,r1), ac[c][1] = (r2,r3) for column c0+c.
template<int NIT>
__device__ __forceinline__ void seg2(
    u64 (&ac)[4][2],
    const float (*__restrict__ X)[BT], const float* __restrict__ W,
    int xrow0, int wrow0, int Ns, int c0)
{
    #pragma unroll 8
    for (int k = 0; k < NIT; ++k) {
        float4 w = *(const float4*)(W + (size_t)(wrow0 + k) * Ns + c0);
        ulonglong2 x = *(const ulonglong2*)&X[xrow0 + k][0];   // (r0,r1),(r2,r3)
        u64 w0 = dup2(w.x), w1 = dup2(w.y), w2 = dup2(w.z), w3 = dup2(w.w);
        ac[0][0] = ffma2u(w0, x.x, ac[0][0]); ac[0][1] = ffma2u(w0, x.y, ac[0][1]);
        ac[1][0] = ffma2u(w1, x.x, ac[1][0]); ac[1][1] = ffma2u(w1, x.y, ac[1][1]);
        ac[2][0] = ffma2u(w2, x.x, ac[2][0]); ac[2][1] = ffma2u(w2, x.y, ac[2][1]);
        ac[3][0] = ffma2u(w3, x.x, ac[3][0]); ac[3][1] = ffma2u(w3, x.y, ac[3][1]);
    }
}

#define PART_STORE()                                                \
    _Pragma("unroll")                                               \
    for (int c = 0; c < 4; ++c) {                                   \
        float4 f;                                                   \
        ((u64*)&f)[0] = ac[c][0]; ((u64*)&f)[1] = ac[c][1];         \
        s->partbuf[t][c] = f;                                       \
    }

#define REDUCE_SUM(NGP, PCH)                                        \
    int gg = t >> 2, cc = t & 3;                                    \
    float4 sv = s->partbuf[gg][cc];                                 \
    _Pragma("unroll 8")                                             \
    for (int pp = 1; pp < (PCH); ++pp) {                            \
        float4 v = s->partbuf[pp * (NGP) + gg][cc];                 \
        sv.x += v.x; sv.y += v.y; sv.z += v.z; sv.w += v.w;         \
    }

// ---------------- precompute kernel: fold weights --------------------------
__global__ void precompute_kernel(
    const float* __restrict__ emb, const float* __restrict__ sel_W,
    const float* __restrict__ bind_W1, const float* __restrict__ succ_W1,
    const float* __restrict__ patch_values, const float* __restrict__ phase_embed)
{
    int idx = blockIdx.x * blockDim.x + threadIdx.x;
    const int N0 = VV * PP;          // TB_SEL
    const int N1 = N0 + VV * HH;     // TB_BIND
    const int N2 = N1 + PP * HH;     // M1
    const int N3 = N2 + PP * HH;     // M2
    const int N4 = N3 + PHD * HH;    // M3
    if (idx < N0) {
        int v = idx / PP, c = idx % PP;
        float acc = 0.f;
        for (int k = 0; k < HH; ++k) acc = fmaf(emb[v * HH + k], sel_W[k * PP + c], acc);
        TB_SEL[v][c] = acc;
    } else if (idx < N1) {
        int i = idx - N0, v = i / HH, c = i % HH;
        float acc = 0.f;
        for (int k = 0; k < HH; ++k) acc = fmaf(emb[v * HH + k], bind_W1[k * HH + c], acc);
        TB_BIND[v][c] = acc;
    } else if (idx < N2) {
        int i = idx - N1, p = i / HH, c = i % HH;
        float acc = 0.f;
        for (int k = 0; k < HH; ++k) acc = fmaf(patch_values[p * HH + k], bind_W1[(HH + k) * HH + c], acc);
        M1[p][c] = acc;
    } else if (idx < N3) {
        int i = idx - N2, p = i / HH, c = i % HH;
        float acc = 0.f;
        for (int k = 0; k < HH; ++k) acc = fmaf(patch_values[p * HH + k], succ_W1[(HH + k) * HH + c], acc);
        M2[p][c] = acc;
    } else if (idx < N4) {
        int i = idx - N3, q = i / HH, c = i % HH;
        float acc = 0.f;
        for (int k = 0; k < HH; ++k) acc = fmaf(phase_embed[q * HH + k], succ_W1[(2 * HH + k) * HH + c], acc);
        M3[q][c] = acc;
    }
}

// ---------------- main recurrence kernel -----------------------------------
__global__ __launch_bounds__(NTH, 1)
void spike_recurrence_kernel(
    const int*   __restrict__ input_ids,
    const float* __restrict__ sel_W,  const float* __restrict__ sel_b,
    const float* __restrict__ bind_W1, const float* __restrict__ bind_b1,
    const float* __restrict__ bind_W2, const float* __restrict__ bind_b2,
    const float* __restrict__ router_W, const float* __restrict__ router_b,
    const float* __restrict__ succ_W1, const float* __restrict__ succ_b1,
    const float* __restrict__ succ_W2, const float* __restrict__ succ_b2,
    const float* __restrict__ gate_W1, const float* __restrict__ gate_b1,
    const float* __restrict__ gate_W2, const float* __restrict__ gate_b2,
    const float* __restrict__ ln_g,   const float* __restrict__ ln_b,
    const float* __restrict__ dec_W,
    float* __restrict__ out)
{
    extern __shared__ __align__(16) char smraw[];
    SMLayout* s = (SMLayout*)smraw;

    const int t    = threadIdx.x;
    const int lane = t & 31;
    const int warp = t >> 5;
    const int bbase = blockIdx.x * BT;

    for (int i = t; i < BT * SSL; i += NTH) {
        int r = i / SSL, ss = i % SSL;
        s->sidx[r][ss] = input_ids[(bbase + r) * SSL + ss];
    }
    if (t < HH) *(float4*)&s->prevb[t][0] = make_float4(0.f, 0.f, 0.f, 0.f);
    __syncthreads();

    const size_t OFF_HID = (size_t)BB * SSL * VV;
    const size_t OFF_PW  = OFF_HID + (size_t)BB * SSL * HH;
    const size_t OFF_PHW = OFF_PW  + (size_t)BB * SSL * PP;
    const size_t OFF_GT  = OFF_PHW + (size_t)BB * SSL * PHD;

    const float* selWp  = sel_W  + HH * PP;         // prev part rows 192..383
    const float* bindWp = bind_W1 + 2 * (size_t)HH * HH;  // prev part rows 384..575
    const float* gateWp = gate_W1 + (size_t)HH * HH;       // prev part rows 192..383
    const float* routWp = router_W + (size_t)HH * PHD;     // prev part rows 192..383

    for (int st = 0; st < SSL; ++st) {
        // ---- gather folded token tables ----------------------------------
        {
            int id0 = s->sidx[0][st], id1 = s->sidx[1][st],
                id2 = s->sidx[2][st], id3 = s->sidx[3][st];
            if (t < PP * BT) {
                int c = t % PP, r = t / PP;
                int id = (r == 0) ? id0 : (r == 1) ? id1 : (r == 2) ? id2 : id3;
                s->tsel[c][r] = TB_SEL[id][c];
            }
            for (int i = t; i < HH * BT; i += NTH) {
                int c = i % HH, r = i / HH;
                int id = (r == 0) ? id0 : (r == 1) ? id1 : (r == 2) ? id2 : id3;
                s->tbind[c][r] = TB_BIND[id][c];
            }
        }
        __syncthreads();

        // ---- sel: prev @ selWp + tsel  (N=64, NG=16, P=24, 8 rows) --------
        {
            int g = t % 16, p = t / 16, c0 = 4 * g;
            u64 ac[4][2] = {};
            seg2<8>(ac, s->prevb, selWp, p * 8, p * 8, PP, c0);
            PART_STORE();
        }
        __syncthreads();
        if (t < PP) {
            REDUCE_SUM(16, 24);
            float4 tv = *(const float4*)&s->tsel[t][0];
            float bias = sel_b[t];
            sv.x += tv.x + bias; sv.y += tv.y + bias;
            sv.z += tv.z + bias; sv.w += tv.w + bias;
            *(float4*)&s->pwb[t][0] = sv;
        }
        __syncthreads();
        if (warp < BT) {   // softmax over 64
            int r = warp;
            float v0 = s->pwb[lane][r], v1 = s->pwb[lane + 32][r];
            float m = fmaxf(v0, v1);
            #pragma unroll
            for (int o = 16; o > 0; o >>= 1) m = fmaxf(m, __shfl_xor_sync(0xffffffffu, m, o));
            float e0 = expf(v0 - m), e1 = expf(v1 - m);
            float sm = e0 + e1;
            #pragma unroll
            for (int o = 16; o > 0; o >>= 1) sm += __shfl_xor_sync(0xffffffffu, sm, o);
            float inv = 1.0f / sm;
            e0 *= inv; e1 *= inv;
            s->pwb[lane][r] = e0; s->pwb[lane + 32][r] = e1;
            size_t ob = OFF_PW + ((size_t)(bbase + r) * SSL + st) * PP;
            out[ob + lane] = e0; out[ob + lane + 32] = e1;
        }
        __syncthreads();

        // ---- bind1: prev @ bindWp + pw @ M1 + tbind -> gelu ---------------
        {
            int g = t % 48, p = t / 48, c0 = 4 * g;
            u64 ac[4][2] = {};
            seg2<24>(ac, s->prevb, bindWp,   p * 24, p * 24, HH, c0);
            seg2<8> (ac, s->pwb,   &M1[0][0], p * 8,  p * 8,  HH, c0);
            PART_STORE();
        }
        __syncthreads();
        if (t < HH) {
            REDUCE_SUM(48, 8);
            float4 tv = *(const float4*)&s->tbind[t][0];
            float b1 = bind_b1[t];
            float4 h;
            h.x = gelu_exact(sv.x + tv.x + b1); h.y = gelu_exact(sv.y + tv.y + b1);
            h.z = gelu_exact(sv.z + tv.z + b1); h.w = gelu_exact(sv.w + tv.w + b1);
            *(float4*)&s->htmp[t][0] = h;
        }
        __syncthreads();

        // ---- bind2 -> tanh -> sec -----------------------------------------
        {
            int g = t % 48, p = t / 48, c0 = 4 * g;
            u64 ac[4][2] = {};
            seg2<24>(ac, s->htmp, bind_W2, p * 24, p * 24, HH, c0);
            PART_STORE();
        }
        __syncthreads();
        if (t < HH) {
            REDUCE_SUM(48, 8);
            float b2 = bind_b2[t];
            float4 h;
            h.x = tanhf(sv.x + b2); h.y = tanhf(sv.y + b2);
            h.z = tanhf(sv.z + b2); h.w = tanhf(sv.w + b2);
            *(float4*)&s->sec[t][0] = h;
        }
        __syncthreads();

        // ---- router: [sec,prev] @ router_W  (N=16, NG=4, P=96) -------------
        {
            int g = t % 4, p = t / 4, c0 = 4 * g;
            u64 ac[4][2] = {};
            seg2<2>(ac, s->sec,   router_W, p * 2, p * 2, PHD, c0);
            seg2<2>(ac, s->prevb, routWp,   p * 2, p * 2, PHD, c0);
            PART_STORE();
        }
        __syncthreads();
        if (t < PHD) {
            REDUCE_SUM(4, 96);
            float bias = router_b[t];
            sv.x += bias; sv.y += bias; sv.z += bias; sv.w += bias;
            *(float4*)&s->rlog[t][0] = sv;
        }
        __syncthreads();
        if (t < BT) {
            int r = t;
            float m = -1e30f;
            #pragma unroll
            for (int c = 0; c < PHD; ++c) m = fmaxf(m, s->rlog[c][r]);
            float sm = 0.f;
            float e[PHD];
            #pragma unroll
            for (int c = 0; c < PHD; ++c) { e[c] = expf(s->rlog[c][r] - m); sm += e[c]; }
            float inv = 1.0f / sm;
            size_t ob = OFF_PHW + ((size_t)(bbase + r) * SSL + st) * PHD;
            #pragma unroll
            for (int c = 0; c < PHD; ++c) {
                float v = e[c] * inv;
                s->phwb[c][r] = v;
                out[ob + c] = v;
            }
        }
        __syncthreads();

        // ---- succ1: sec @ W + pw @ M2 + phw @ M3 -> gelu --------------------
        {
            int g = t % 48, p = t / 48, c0 = 4 * g;
            u64 ac[4][2] = {};
            seg2<24>(ac, s->sec,  succ_W1,   p * 24, p * 24, HH, c0);
            seg2<8> (ac, s->pwb,  &M2[0][0], p * 8,  p * 8,  HH, c0);
            seg2<2> (ac, s->phwb, &M3[0][0], p * 2,  p * 2,  HH, c0);
            PART_STORE();
        }
        __syncthreads();
        if (t < HH) {
            REDUCE_SUM(48, 8);
            float b1 = succ_b1[t];
            float4 h;
            h.x = gelu_exact(sv.x + b1); h.y = gelu_exact(sv.y + b1);
            h.z = gelu_exact(sv.z + b1); h.w = gelu_exact(sv.w + b1);
            *(float4*)&s->htmp[t][0] = h;
        }
        __syncthreads();

        // ---- succ2 -> tanh -> succ ------------------------------------------
        {
            int g = t % 48, p = t / 48, c0 = 4 * g;
            u64 ac[4][2] = {};
            seg2<24>(ac, s->htmp, succ_W2, p * 24, p * 24, HH, c0);
            PART_STORE();
        }
        __syncthreads();
        if (t < HH) {
            REDUCE_SUM(48, 8);
            float b2 = succ_b2[t];
            float4 h;
            h.x = tanhf(sv.x + b2); h.y = tanhf(sv.y + b2);
            h.z = tanhf(sv.z + b2); h.w = tanhf(sv.w + b2);
            *(float4*)&s->succ[t][0] = h;
        }
        __syncthreads();

        // ---- gate: [succ,prev] @ gate_W1 -> gelu * gate_W2 -------------------
        {
            int g = t % 48, p = t / 48, c0 = 4 * g;
            u64 ac[4][2] = {};
            seg2<24>(ac, s->succ,  gate_W1, p * 24, p * 24, HH, c0);
            seg2<24>(ac, s->prevb, gateWp,  p * 24, p * 24, HH, c0);
            PART_STORE();
        }
        __syncthreads();
        if (t < HH) {
            REDUCE_SUM(48, 8);
            float b1 = gate_b1[t];
            float w2 = gate_W2[t];
            float4 h;
            h.x = gelu_exact(sv.x + b1) * w2; h.y = gelu_exact(sv.y + b1) * w2;
            h.z = gelu_exact(sv.z + b1) * w2; h.w = gelu_exact(sv.w + b1) * w2;
            *(float4*)&s->htmp[t][0] = h;
        }
        __syncthreads();
        if (warp < BT) {
            int r = warp;
            float sg = 0.f;
            #pragma unroll
            for (int j = 0; j < 6; ++j) sg += s->htmp[lane + 32 * j][r];
            #pragma unroll
            for (int o = 16; o > 0; o >>= 1) sg += __shfl_xor_sync(0xffffffffu, sg, o);
            if (lane == 0) {
                float gv = sigmoidf_(sg + gate_b2[0]);
                s->gatev[r] = gv;
                out[OFF_GT + (size_t)(bbase + r) * SSL + st] = gv;
            }
        }
        __syncthreads();

        // ---- hidden blend + LayerNorm ----------------------------------------
        if (t < HH) {
            float4 svv = *(const float4*)&s->succ[t][0];
            float4 pv  = *(const float4*)&s->prevb[t][0];
            float4 h;
            h.x = s->gatev[0] * svv.x + (1.f - s->gatev[0]) * pv.x;
            h.y = s->gatev[1] * svv.y + (1.f - s->gatev[1]) * pv.y;
            h.z = s->gatev[2] * svv.z + (1.f - s->gatev[2]) * pv.z;
            h.w = s->gatev[3] * svv.w + (1.f - s->gatev[3]) * pv.w;
            *(float4*)&s->htmp[t][0] = h;
        }
        __syncthreads();
        if (warp < BT) {
            int r = warp;
            float sm = 0.f, sq = 0.f;
            #pragma unroll
            for (int j = 0; j < 6; ++j) {
                float v = s->htmp[lane + 32 * j][r];
                sm += v; sq += v * v;
            }
            #pragma unroll
            for (int o = 16; o > 0; o >>= 1) {
                sm += __shfl_xor_sync(0xffffffffu, sm, o);
                sq += __shfl_xor_sync(0xffffffffu, sq, o);
            }
            if (lane == 0) {
                float mean = sm * (1.0f / HH);
                float var  = sq * (1.0f / HH) - mean * mean;
                s->lnmean[r] = mean;
                s->lnrstd[r] = rsqrtf(var + 1e-5f);
            }
        }
        __syncthreads();
        if (t < HH) {
            float g = ln_g[t], bb = ln_b[t];
            float4 h = *(const float4*)&s->htmp[t][0];
            float4 o;
            o.x = (h.x - s->lnmean[0]) * s->lnrstd[0] * g + bb;
            o.y = (h.y - s->lnmean[1]) * s->lnrstd[1] * g + bb;
            o.z = (h.z - s->lnmean[2]) * s->lnrstd[2] * g + bb;
            o.w = (h.w - s->lnmean[3]) * s->lnrstd[3] * g + bb;
            *(float4*)&s->prevb[t][0] = o;   // carry
            #pragma unroll
            for (int r = 0; r < BT; ++r)
                out[OFF_HID + ((size_t)(bbase + r) * SSL + st) * HH + t] =
                    (r == 0) ? o.x : (r == 1) ? o.y : (r == 2) ? o.z : o.w;
        }
        __syncthreads();

        // ---- decoder logits (N=256, NG=64, P=6, 32 rows) ----------------------
        {
            int g = t % 64, p = t / 64, c0 = 4 * g;
            u64 ac[4][2] = {};
            seg2<32>(ac, s->prevb, dec_W, p * 32, p * 32, VV, c0);
            PART_STORE();
        }
        __syncthreads();
        if (t < VV) {
            REDUCE_SUM(64, 6);
            #pragma unroll
            for (int r = 0; r < BT; ++r) {
                size_t ob = ((size_t)(bbase + r) * SSL + st) * VV;
                float v = (r == 0) ? sv.x : (r == 1) ? sv.y : (r == 2) ? sv.z : sv.w;
                out[ob + t] = v;
            }
        }
        __syncthreads();
    }
}

extern "C" void kernel_launch(void* const* d_in, const int* in_sizes, int n_in,
                              void* d_out, int out_size) {
    const int*   input_ids    = (const int*)  d_in[0];
    const float* emb          = (const float*)d_in[1];
    const float* sel_W        = (const float*)d_in[2];
    const float* sel_b        = (const float*)d_in[3];
    const float* patch_values = (const float*)d_in[4];
    const float* bind_W1      = (const float*)d_in[5];
    const float* bind_b1      = (const float*)d_in[6];
    const float* bind_W2      = (const float*)d_in[7];
    const float* bind_b2      = (const float*)d_in[8];
    const float* phase_embed  = (const float*)d_in[9];
    const float* router_W     = (const float*)d_in[10];
    const float* router_b     = (const float*)d_in[11];
    const float* succ_W1      = (const float*)d_in[12];
    const float* succ_b1      = (const float*)d_in[13];
    const float* succ_W2      = (const float*)d_in[14];
    const float* succ_b2      = (const float*)d_in[15];
    const float* gate_W1      = (const float*)d_in[16];
    const float* gate_b1      = (const float*)d_in[17];
    const float* gate_W2      = (const float*)d_in[18];
    const float* gate_b2      = (const float*)d_in[19];
    const float* ln_g         = (const float*)d_in[20];
    const float* ln_b         = (const float*)d_in[21];
    const float* dec_W        = (const float*)d_in[22];
    float* out = (float*)d_out;

    // fold weights (deterministic, graph-capturable)
    int total = VV * PP + VV * HH + 2 * PP * HH + PHD * HH;
    precompute_kernel<<<(total + 255) / 256, 256>>>(
        emb, sel_W, bind_W1, succ_W1, patch_values, phase_embed);

    cudaFuncSetAttribute(spike_recurrence_kernel,
                         cudaFuncAttributeMaxDynamicSharedMemorySize,
                         (int)sizeof(SMLayout));

    spike_recurrence_kernel<<<BB / BT, NTH, sizeof(SMLayout)>>>(
        input_ids, sel_W, sel_b,
        bind_W1, bind_b1, bind_W2, bind_b2,
        router_W, router_b,
        succ_W1, succ_b1, succ_W2, succ_b2,
        gate_W1, gate_b1, gate_W2, gate_b2,
        ln_g, ln_b, dec_W, out);
}

// round 8
// speedup vs baseline: 2.1029x; 1.0498x over previous
#include <cuda_runtime.h>
#include <math.h>
#include <cstdint>

#define BB  512
#define SSL 128
#define HH  192
#define VV  256
#define PP  64
#define PHD 16
#define BT  4
#define NTH 384

typedef unsigned long long u64;

// Precomputed folded weights
__device__ float TB_SEL[VV][PP];    // emb @ sel_W[0:192]
__device__ float TB_BIND[VV][HH];   // emb @ bind_W1[0:192]
__device__ float M1[PP][HH];        // patch_values @ bind_W1[192:384]
__device__ float M2[PP][HH];        // patch_values @ succ_W1[192:384]
__device__ float M3[PHD][HH];       // phase_embed  @ succ_W1[384:576]

struct SMLayout {
    float prevb[HH][BT];
    float sec  [HH][BT];
    float succ [HH][BT];
    float htmp [HH][BT];
    float tsel [PP][BT];
    float tbind[HH][BT];
    float pwb  [PP][BT];
    float phwb [PHD][BT];
    float rlog [PHD][BT];
    float4 partbuf[NTH][4];
    float gatev[BT];
    float lnmean[BT], lnrstd[BT];
    int   sidx[BT][SSL];
};

__device__ __forceinline__ float gelu_exact(float x) {
    return 0.5f * x * (1.0f + erff(x * 0.70710678118654752440f));
}
__device__ __forceinline__ float sigmoidf_(float x) {
    return 1.0f / (1.0f + expf(-x));
}
__device__ __forceinline__ u64 ffma2u(u64 a, u64 b, u64 c) {
    u64 d;
    asm("fma.rn.f32x2 %0, %1, %2, %3;" : "=l"(d) : "l"(a), "l"(b), "l"(c));
    return d;
}
__device__ __forceinline__ u64 dup2(float w) {
    u64 d;
    asm("mov.b64 %0, {%1, %1};" : "=l"(d) : "f"(w));
    return d;
}

// 4 cols x 4 rows tile; rows held as 2 f32x2 pairs per column.
template<int NIT>
__device__ __forceinline__ void seg2(
    u64 (&ac)[4][2],
    const float (*__restrict__ X)[BT], const float* __restrict__ W,
    int xrow0, int wrow0, int Ns, int c0)
{
    #pragma unroll 8
    for (int k = 0; k < NIT; ++k) {
        float4 w = *(const float4*)(W + (size_t)(wrow0 + k) * Ns + c0);
        ulonglong2 x = *(const ulonglong2*)&X[xrow0 + k][0];
        u64 w0 = dup2(w.x), w1 = dup2(w.y), w2 = dup2(w.z), w3 = dup2(w.w);
        ac[0][0] = ffma2u(w0, x.x, ac[0][0]); ac[0][1] = ffma2u(w0, x.y, ac[0][1]);
        ac[1][0] = ffma2u(w1, x.x, ac[1][0]); ac[1][1] = ffma2u(w1, x.y, ac[1][1]);
        ac[2][0] = ffma2u(w2, x.x, ac[2][0]); ac[2][1] = ffma2u(w2, x.y, ac[2][1]);
        ac[3][0] = ffma2u(w3, x.x, ac[3][0]); ac[3][1] = ffma2u(w3, x.y, ac[3][1]);
    }
}

#define PART_STORE()                                                \
    _Pragma("unroll")                                               \
    for (int c = 0; c < 4; ++c) {                                   \
        float4 f;                                                   \
        ((u64*)&f)[0] = ac[c][0]; ((u64*)&f)[1] = ac[c][1];         \
        s->partbuf[t][c] = f;                                       \
    }

// spread reduce: 2 threads per column (float2 halves); col = t>>1, h = t&1
#define REDUCE2(NGP, PCH, COL, H)                                           \
    int gg = (COL) >> 2, cc = (COL) & 3;                                    \
    float2 sv = *(const float2*)((const float*)&s->partbuf[gg][cc] + 2*(H));\
    _Pragma("unroll 8")                                                     \
    for (int pp = 1; pp < (PCH); ++pp) {                                    \
        float2 v = *(const float2*)((const float*)&s->partbuf[pp * (NGP) + gg][cc] + 2*(H)); \
        sv.x += v.x; sv.y += v.y;                                           \
    }

// ---------------- precompute kernel ----------------------------------------
__global__ void precompute_kernel(
    const float* __restrict__ emb, const float* __restrict__ sel_W,
    const float* __restrict__ bind_W1, const float* __restrict__ succ_W1,
    const float* __restrict__ patch_values, const float* __restrict__ phase_embed)
{
    int idx = blockIdx.x * blockDim.x + threadIdx.x;
    const int N0 = VV * PP;
    const int N1 = N0 + VV * HH;
    const int N2 = N1 + PP * HH;
    const int N3 = N2 + PP * HH;
    const int N4 = N3 + PHD * HH;
    if (idx < N0) {
        int v = idx / PP, c = idx % PP;
        float acc = 0.f;
        for (int k = 0; k < HH; ++k) acc = fmaf(emb[v * HH + k], sel_W[k * PP + c], acc);
        TB_SEL[v][c] = acc;
    } else if (idx < N1) {
        int i = idx - N0, v = i / HH, c = i % HH;
        float acc = 0.f;
        for (int k = 0; k < HH; ++k) acc = fmaf(emb[v * HH + k], bind_W1[k * HH + c], acc);
        TB_BIND[v][c] = acc;
    } else if (idx < N2) {
        int i = idx - N1, p = i / HH, c = i % HH;
        float acc = 0.f;
        for (int k = 0; k < HH; ++k) acc = fmaf(patch_values[p * HH + k], bind_W1[(HH + k) * HH + c], acc);
        M1[p][c] = acc;
    } else if (idx < N3) {
        int i = idx - N2, p = i / HH, c = i % HH;
        float acc = 0.f;
        for (int k = 0; k < HH; ++k) acc = fmaf(patch_values[p * HH + k], succ_W1[(HH + k) * HH + c], acc);
        M2[p][c] = acc;
    } else if (idx < N4) {
        int i = idx - N3, q = i / HH, c = i % HH;
        float acc = 0.f;
        for (int k = 0; k < HH; ++k) acc = fmaf(phase_embed[q * HH + k], succ_W1[(2 * HH + k) * HH + c], acc);
        M3[q][c] = acc;
    }
}

// ---------------- decoder kernel: logits = hidden @ dec_W ------------------
#define DROWS 64
#define DTH   512
__global__ __launch_bounds__(DTH, 1)
void decoder_kernel(const float* __restrict__ hidden,   // [BS, HH] row-major
                    const float* __restrict__ dec_W,    // [HH, VV]
                    float* __restrict__ logits)         // [BS, VV]
{
    __shared__ float hid[HH][DROWS];   // transposed tile: 192*64*4 = 48KB
    const int t = threadIdx.x;
    const size_t row0 = (size_t)blockIdx.x * DROWS;

    // coalesced load + transpose
    for (int i = t; i < DROWS * (HH / 4); i += DTH) {
        int r = i / (HH / 4), kq = i % (HH / 4);
        float4 v = *(const float4*)&hidden[(row0 + r) * HH + 4 * kq];
        hid[4 * kq + 0][r] = v.x; hid[4 * kq + 1][r] = v.y;
        hid[4 * kq + 2][r] = v.z; hid[4 * kq + 3][r] = v.w;
    }
    __syncthreads();

    const int cg = t % 64, rg = t / 64;   // 64 col-groups x 8 row-groups
    const int c0 = 4 * cg, r0 = 8 * rg;
    u64 ac[4][4] = {};
    #pragma unroll 4
    for (int k = 0; k < HH; ++k) {
        float4 w = *(const float4*)&dec_W[(size_t)k * VV + c0];
        ulonglong2 xa = *(const ulonglong2*)&hid[k][r0];
        ulonglong2 xb = *(const ulonglong2*)&hid[k][r0 + 4];
        u64 w0 = dup2(w.x), w1 = dup2(w.y), w2 = dup2(w.z), w3 = dup2(w.w);
        ac[0][0] = ffma2u(w0, xa.x, ac[0][0]); ac[0][1] = ffma2u(w0, xa.y, ac[0][1]);
        ac[0][2] = ffma2u(w0, xb.x, ac[0][2]); ac[0][3] = ffma2u(w0, xb.y, ac[0][3]);
        ac[1][0] = ffma2u(w1, xa.x, ac[1][0]); ac[1][1] = ffma2u(w1, xa.y, ac[1][1]);
        ac[1][2] = ffma2u(w1, xb.x, ac[1][2]); ac[1][3] = ffma2u(w1, xb.y, ac[1][3]);
        ac[2][0] = ffma2u(w2, xa.x, ac[2][0]); ac[2][1] = ffma2u(w2, xa.y, ac[2][1]);
        ac[2][2] = ffma2u(w2, xb.x, ac[2][2]); ac[2][3] = ffma2u(w2, xb.y, ac[2][3]);
        ac[3][0] = ffma2u(w3, xa.x, ac[3][0]); ac[3][1] = ffma2u(w3, xa.y, ac[3][1]);
        ac[3][2] = ffma2u(w3, xb.x, ac[3][2]); ac[3][3] = ffma2u(w3, xb.y, ac[3][3]);
    }
    // write 8 rows x 4 cols as STG.128 per row
    #pragma unroll
    for (int p = 0; p < 4; ++p) {
        #pragma unroll
        for (int j = 0; j < 2; ++j) {
            int r = r0 + 2 * p + j;
            float4 o;
            o.x = ((float*)&ac[0][p])[j]; o.y = ((float*)&ac[1][p])[j];
            o.z = ((float*)&ac[2][p])[j]; o.w = ((float*)&ac[3][p])[j];
            *(float4*)&logits[(row0 + r) * VV + c0] = o;
        }
    }
}

// ---------------- main recurrence kernel -----------------------------------
__global__ __launch_bounds__(NTH, 1)
void spike_recurrence_kernel(
    const int*   __restrict__ input_ids,
    const float* __restrict__ sel_W,  const float* __restrict__ sel_b,
    const float* __restrict__ bind_W1, const float* __restrict__ bind_b1,
    const float* __restrict__ bind_W2, const float* __restrict__ bind_b2,
    const float* __restrict__ router_W, const float* __restrict__ router_b,
    const float* __restrict__ succ_W1, const float* __restrict__ succ_b1,
    const float* __restrict__ succ_W2, const float* __restrict__ succ_b2,
    const float* __restrict__ gate_W1, const float* __restrict__ gate_b1,
    const float* __restrict__ gate_W2, const float* __restrict__ gate_b2,
    const float* __restrict__ ln_g,   const float* __restrict__ ln_b,
    float* __restrict__ out)
{
    extern __shared__ __align__(16) char smraw[];
    SMLayout* s = (SMLayout*)smraw;

    const int t    = threadIdx.x;
    const int lane = t & 31;
    const int warp = t >> 5;
    const int bbase = blockIdx.x * BT;
    const int col2 = t >> 1, hh2 = t & 1;   // spread-reduce mapping

    for (int i = t; i < BT * SSL; i += NTH) {
        int r = i / SSL, ss = i % SSL;
        s->sidx[r][ss] = input_ids[(bbase + r) * SSL + ss];
    }
    if (t < HH) *(float4*)&s->prevb[t][0] = make_float4(0.f, 0.f, 0.f, 0.f);
    __syncthreads();

    const size_t OFF_HID = (size_t)BB * SSL * VV;
    const size_t OFF_PW  = OFF_HID + (size_t)BB * SSL * HH;
    const size_t OFF_PHW = OFF_PW  + (size_t)BB * SSL * PP;
    const size_t OFF_GT  = OFF_PHW + (size_t)BB * SSL * PHD;

    const float* selWp  = sel_W  + HH * PP;
    const float* bindWp = bind_W1 + 2 * (size_t)HH * HH;
    const float* gateWp = gate_W1 + (size_t)HH * HH;
    const float* routWp = router_W + (size_t)HH * PHD;

    for (int st = 0; st < SSL; ++st) {
        // ---- gather folded token tables ----------------------------------
        {
            int id0 = s->sidx[0][st], id1 = s->sidx[1][st],
                id2 = s->sidx[2][st], id3 = s->sidx[3][st];
            if (t < PP * BT) {
                int c = t % PP, r = t / PP;
                int id = (r == 0) ? id0 : (r == 1) ? id1 : (r == 2) ? id2 : id3;
                s->tsel[c][r] = TB_SEL[id][c];
            }
            for (int i = t; i < HH * BT; i += NTH) {
                int c = i % HH, r = i / HH;
                int id = (r == 0) ? id0 : (r == 1) ? id1 : (r == 2) ? id2 : id3;
                s->tbind[c][r] = TB_BIND[id][c];
            }
        }
        __syncthreads();

        // ---- sel: prev @ selWp + tsel  (N=64, NG=16, P=24) ----------------
        {
            int g = t % 16, p = t / 16, c0 = 4 * g;
            u64 ac[4][2] = {};
            seg2<8>(ac, s->prevb, selWp, p * 8, p * 8, PP, c0);
            PART_STORE();
        }
        __syncthreads();
        if (t < 2 * PP) {
            REDUCE2(16, 24, col2, hh2);
            float2 tv = *(const float2*)&s->tsel[col2][2 * hh2];
            float bias = sel_b[col2];
            sv.x += tv.x + bias; sv.y += tv.y + bias;
            *(float2*)&s->pwb[col2][2 * hh2] = sv;
        }
        __syncthreads();
        if (warp < BT) {   // softmax over 64
            int r = warp;
            float v0 = s->pwb[lane][r], v1 = s->pwb[lane + 32][r];
            float m = fmaxf(v0, v1);
            #pragma unroll
            for (int o = 16; o > 0; o >>= 1) m = fmaxf(m, __shfl_xor_sync(0xffffffffu, m, o));
            float e0 = expf(v0 - m), e1 = expf(v1 - m);
            float sm = e0 + e1;
            #pragma unroll
            for (int o = 16; o > 0; o >>= 1) sm += __shfl_xor_sync(0xffffffffu, sm, o);
            float inv = 1.0f / sm;
            e0 *= inv; e1 *= inv;
            s->pwb[lane][r] = e0; s->pwb[lane + 32][r] = e1;
            size_t ob = OFF_PW + ((size_t)(bbase + r) * SSL + st) * PP;
            out[ob + lane] = e0; out[ob + lane + 32] = e1;
        }
        __syncthreads();

        // ---- bind1: prev @ bindWp + pw @ M1 + tbind -> gelu ---------------
        {
            int g = t % 48, p = t / 48, c0 = 4 * g;
            u64 ac[4][2] = {};
            seg2<24>(ac, s->prevb, bindWp,    p * 24, p * 24, HH, c0);
            seg2<8> (ac, s->pwb,   &M1[0][0], p * 8,  p * 8,  HH, c0);
            PART_STORE();
        }
        __syncthreads();
        {
            REDUCE2(48, 8, col2, hh2);
            float2 tv = *(const float2*)&s->tbind[col2][2 * hh2];
            float b1 = bind_b1[col2];
            float2 h;
            h.x = gelu_exact(sv.x + tv.x + b1); h.y = gelu_exact(sv.y + tv.y + b1);
            *(float2*)&s->htmp[col2][2 * hh2] = h;
        }
        __syncthreads();

        // ---- bind2 -> tanh -> sec -----------------------------------------
        {
            int g = t % 48, p = t / 48, c0 = 4 * g;
            u64 ac[4][2] = {};
            seg2<24>(ac, s->htmp, bind_W2, p * 24, p * 24, HH, c0);
            PART_STORE();
        }
        __syncthreads();
        {
            REDUCE2(48, 8, col2, hh2);
            float b2 = bind_b2[col2];
            float2 h;
            h.x = tanhf(sv.x + b2); h.y = tanhf(sv.y + b2);
            *(float2*)&s->sec[col2][2 * hh2] = h;
        }
        __syncthreads();

        // ---- router: [sec,prev] @ router_W  (N=16, NG=4, P=96) -------------
        {
            int g = t % 4, p = t / 4, c0 = 4 * g;
            u64 ac[4][2] = {};
            seg2<2>(ac, s->sec,   router_W, p * 2, p * 2, PHD, c0);
            seg2<2>(ac, s->prevb, routWp,   p * 2, p * 2, PHD, c0);
            PART_STORE();
        }
        __syncthreads();
        if (t < 2 * PHD) {
            REDUCE2(4, 96, col2, hh2);
            float bias = router_b[col2];
            sv.x += bias; sv.y += bias;
            *(float2*)&s->rlog[col2][2 * hh2] = sv;
        }
        __syncthreads();
        if (t < BT) {
            int r = t;
            float m = -1e30f;
            #pragma unroll
            for (int c = 0; c < PHD; ++c) m = fmaxf(m, s->rlog[c][r]);
            float sm = 0.f;
            float e[PHD];
            #pragma unroll
            for (int c = 0; c < PHD; ++c) { e[c] = expf(s->rlog[c][r] - m); sm += e[c]; }
            float inv = 1.0f / sm;
            size_t ob = OFF_PHW + ((size_t)(bbase + r) * SSL + st) * PHD;
            #pragma unroll
            for (int c = 0; c < PHD; ++c) {
                float v = e[c] * inv;
                s->phwb[c][r] = v;
                out[ob + c] = v;
            }
        }
        __syncthreads();

        // ---- succ1: sec @ W + pw @ M2 + phw @ M3 -> gelu --------------------
        {
            int g = t % 48, p = t / 48, c0 = 4 * g;
            u64 ac[4][2] = {};
            seg2<24>(ac, s->sec,  succ_W1,   p * 24, p * 24, HH, c0);
            seg2<8> (ac, s->pwb,  &M2[0][0], p * 8,  p * 8,  HH, c0);
            seg2<2> (ac, s->phwb, &M3[0][0], p * 2,  p * 2,  HH, c0);
            PART_STORE();
        }
        __syncthreads();
        {
            REDUCE2(48, 8, col2, hh2);
            float b1 = succ_b1[col2];
            float2 h;
            h.x = gelu_exact(sv.x + b1); h.y = gelu_exact(sv.y + b1);
            *(float2*)&s->htmp[col2][2 * hh2] = h;
        }
        __syncthreads();

        // ---- succ2 -> tanh -> succ ------------------------------------------
        {
            int g = t % 48, p = t / 48, c0 = 4 * g;
            u64 ac[4][2] = {};
            seg2<24>(ac, s->htmp, succ_W2, p * 24, p * 24, HH, c0);
            PART_STORE();
        }
        __syncthreads();
        {
            REDUCE2(48, 8, col2, hh2);
            float b2 = succ_b2[col2];
            float2 h;
            h.x = tanhf(sv.x + b2); h.y = tanhf(sv.y + b2);
            *(float2*)&s->succ[col2][2 * hh2] = h;
        }
        __syncthreads();

        // ---- gate: [succ,prev] @ gate_W1 -> gelu * gate_W2 -------------------
        {
            int g = t % 48, p = t / 48, c0 = 4 * g;
            u64 ac[4][2] = {};
            seg2<24>(ac, s->succ,  gate_W1, p * 24, p * 24, HH, c0);
            seg2<24>(ac, s->prevb, gateWp,  p * 24, p * 24, HH, c0);
            PART_STORE();
        }
        __syncthreads();
        {
            REDUCE2(48, 8, col2, hh2);
            float b1 = gate_b1[col2];
            float w2 = gate_W2[col2];
            float2 h;
            h.x = gelu_exact(sv.x + b1) * w2; h.y = gelu_exact(sv.y + b1) * w2;
            *(float2*)&s->htmp[col2][2 * hh2] = h;
        }
        __syncthreads();
        if (warp < BT) {
            int r = warp;
            float sg = 0.f;
            #pragma unroll
            for (int j = 0; j < 6; ++j) sg += s->htmp[lane + 32 * j][r];
            #pragma unroll
            for (int o = 16; o > 0; o >>= 1) sg += __shfl_xor_sync(0xffffffffu, sg, o);
            if (lane == 0) {
                float gv = sigmoidf_(sg + gate_b2[0]);
                s->gatev[r] = gv;
                out[OFF_GT + (size_t)(bbase + r) * SSL + st] = gv;
            }
        }
        __syncthreads();

        // ---- hidden blend + LayerNorm ----------------------------------------
        if (t < HH) {
            float4 svv = *(const float4*)&s->succ[t][0];
            float4 pv  = *(const float4*)&s->prevb[t][0];
            float4 h;
            h.x = s->gatev[0] * svv.x + (1.f - s->gatev[0]) * pv.x;
            h.y = s->gatev[1] * svv.y + (1.f - s->gatev[1]) * pv.y;
            h.z = s->gatev[2] * svv.z + (1.f - s->gatev[2]) * pv.z;
            h.w = s->gatev[3] * svv.w + (1.f - s->gatev[3]) * pv.w;
            *(float4*)&s->htmp[t][0] = h;
        }
        __syncthreads();
        if (warp < BT) {
            int r = warp;
            float sm = 0.f, sq = 0.f;
            #pragma unroll
            for (int j = 0; j < 6; ++j) {
                float v = s->htmp[lane + 32 * j][r];
                sm += v; sq += v * v;
            }
            #pragma unroll
            for (int o = 16; o > 0; o >>= 1) {
                sm += __shfl_xor_sync(0xffffffffu, sm, o);
                sq += __shfl_xor_sync(0xffffffffu, sq, o);
            }
            if (lane == 0) {
                float mean = sm * (1.0f / HH);
                float var  = sq * (1.0f / HH) - mean * mean;
                s->lnmean[r] = mean;
                s->lnrstd[r] = rsqrtf(var + 1e-5f);
            }
        }
        __syncthreads();
        if (t < HH) {
            float g = ln_g[t], bb = ln_b[t];
            float4 h = *(const float4*)&s->htmp[t][0];
            float4 o;
            o.x = (h.x - s->lnmean[0]) * s->lnrstd[0] * g + bb;
            o.y = (h.y - s->lnmean[1]) * s->lnrstd[1] * g + bb;
            o.z = (h.z - s->lnmean[2]) * s->lnrstd[2] * g + bb;
            o.w = (h.w - s->lnmean[3]) * s->lnrstd[3] * g + bb;
            *(float4*)&s->prevb[t][0] = o;   // carry
            #pragma unroll
            for (int r = 0; r < BT; ++r)
                out[OFF_HID + ((size_t)(bbase + r) * SSL + st) * HH + t] =
                    (r == 0) ? o.x : (r == 1) ? o.y : (r == 2) ? o.z : o.w;
        }
        __syncthreads();
    }
}

extern "C" void kernel_launch(void* const* d_in, const int* in_sizes, int n_in,
                              void* d_out, int out_size) {
    const int*   input_ids    = (const int*)  d_in[0];
    const float* emb          = (const float*)d_in[1];
    const float* sel_W        = (const float*)d_in[2];
    const float* sel_b        = (const float*)d_in[3];
    const float* patch_values = (const float*)d_in[4];
    const float* bind_W1      = (const float*)d_in[5];
    const float* bind_b1      = (const float*)d_in[6];
    const float* bind_W2      = (const float*)d_in[7];
    const float* bind_b2      = (const float*)d_in[8];
    const float* phase_embed  = (const float*)d_in[9];
    const float* router_W     = (const float*)d_in[10];
    const float* router_b     = (const float*)d_in[11];
    const float* succ_W1      = (const float*)d_in[12];
    const float* succ_b1      = (const float*)d_in[13];
    const float* succ_W2      = (const float*)d_in[14];
    const float* succ_b2      = (const float*)d_in[15];
    const float* gate_W1      = (const float*)d_in[16];
    const float* gate_b1      = (const float*)d_in[17];
    const float* gate_W2      = (const float*)d_in[18];
    const float* gate_b2      = (const float*)d_in[19];
    const float* ln_g         = (const float*)d_in[20];
    const float* ln_b         = (const float*)d_in[21];
    const float* dec_W        = (const float*)d_in[22];
    float* out = (float*)d_out;

    int total = VV * PP + VV * HH + 2 * PP * HH + PHD * HH;
    precompute_kernel<<<(total + 255) / 256, 256>>>(
        emb, sel_W, bind_W1, succ_W1, patch_values, phase_embed);

    cudaFuncSetAttribute(spike_recurrence_kernel,
                         cudaFuncAttributeMaxDynamicSharedMemorySize,
                         (int)sizeof(SMLayout));

    spike_recurrence_kernel<<<BB / BT, NTH, sizeof(SMLayout)>>>(
        input_ids, sel_W, sel_b,
        bind_W1, bind_b1, bind_W2, bind_b2,
        router_W, router_b,
        succ_W1, succ_b1, succ_W2, succ_b2,
        gate_W1, gate_b1, gate_W2, gate_b2,
        ln_g, ln_b, out);

    const float* hidden = out + (size_t)BB * SSL * VV;
    decoder_kernel<<<(BB * SSL) / DROWS, DTH>>>(hidden, dec_W, out);
}